// round 2
// baseline (speedup 1.0000x reference)
#include <cuda_runtime.h>

// Problem shape (fixed by the dataset)
#define TT 4096
#define NB 16
#define CC 512
#define NC (NB * CC)            // 8192 columns
#define CHUNK 64
#define NCHUNKS (TT / CHUNK)    // 64
#define NGRP (NC / 256)         // 32 column groups of 256
#define NBLK (NCHUNKS * NGRP)   // 2048 blocks
#define TOTAL (TT * NC)         // 33,554,432 floats for new_x

// Static scratch (no allocations allowed)
__device__ float g_agg[NCHUNKS * NC];   // 2 MB: per-(chunk,column) aggregates
__device__ int   g_flag[NBLK];          // per-block "aggregate published" flag
__device__ float g_rcp[TT * NB];        // 256 KB: 1/(t+1+len_n), layout [t][n]

// k0: reciprocal table + flag reset (flags must reset on every graph replay).
__global__ void k0_prep(const int* __restrict__ cached_len) {
    int idx = blockIdx.x * blockDim.x + threadIdx.x;
    if (idx < NBLK) g_flag[idx] = 0;
    if (idx >= TT * NB) return;
    int n = idx & (NB - 1);
    int t = idx >> 4;
    g_rcp[idx] = 1.0f / ((float)(t + 1) + (float)cached_len[n]);
}

// Single-pass scan with decoupled lookback.
// Block = (chunk, column-group): 256 threads, each owns one column for 64 steps.
// blockIdx.x = chunk*NGRP + g, so all predecessors of a chunk have lower bid
// (in-order CTA dispatch => spin-waits always make progress).
__global__ void k_main(const float* __restrict__ x,
                       const int* __restrict__ cached_len,
                       const float* __restrict__ cached_avg,
                       float* __restrict__ out, int extras) {
    extern __shared__ float sm[];                 // CHUNK * 256 floats = 64 KB
    int bid = blockIdx.x;
    int chunk = bid >> 5;                         // / NGRP
    int g = bid & (NGRP - 1);
    int tid = threadIdx.x;
    int nc = g * 256 + tid;
    int n = nc >> 9;                              // c fastest, C=512

    // Phase 1: stream tile DRAM -> smem, accumulate column sum, publish.
    const float* px = x + (size_t)chunk * CHUNK * NC + nc;
    float s = 0.0f;
#pragma unroll 8
    for (int i = 0; i < CHUNK; i++) {
        float v = px[(size_t)i * NC];
        sm[i * 256 + tid] = v;
        s += v;
    }
    g_agg[chunk * NC + nc] = s;
    __threadfence();
    __syncthreads();
    if (tid == 0) g_flag[bid] = 1;

    // Phase 2: lookback — wait for all predecessor chunks of this column group,
    // then sum their aggregates (L2-resident, coalesced).
    float base = cached_avg[nc] * (float)cached_len[n];
    if (chunk > 0) {
        if (tid < chunk) {
            while (((volatile int*)g_flag)[tid * NGRP + g] == 0) { }
        }
        __syncthreads();
        __threadfence();
        float pref = 0.0f;
        for (int ch = 0; ch < chunk; ch++)
            pref += g_agg[ch * NC + nc];
        base += pref;
    }

    // Phase 3: rescan from smem, scale by precomputed reciprocal, stream out.
    const float* pr = g_rcp + (size_t)chunk * CHUNK * NB + n;   // warp-uniform
    float*       po = out   + (size_t)chunk * CHUNK * NC + nc;
    float last = 0.0f;
#pragma unroll 8
    for (int i = 0; i < CHUNK; i++) {
        base += sm[i * 256 + tid];
        last = base * pr[(size_t)i * NB];
        po[(size_t)i * NC] = last;
    }

    if (extras) {
        // Tuple order: [new_x | new_cached_len (as float) | new_cached_avg]
        if (chunk == NCHUNKS - 1) out[TOTAL + NB + nc] = last;   // new_x[T-1]
        if (bid == 0 && tid < NB) out[TOTAL + tid] = (float)(cached_len[tid] + TT);
    }
}

extern "C" void kernel_launch(void* const* d_in, const int* in_sizes, int n_in,
                              void* d_out, int out_size) {
    const float* x          = (const float*)d_in[0];   // (T, N, C)
    const int*   cached_len = (const int*)d_in[1];     // (N,)
    const float* cached_avg = (const float*)d_in[2];   // (N, C)
    float* out = (float*)d_out;

    int extras = (out_size >= TOTAL + NB + NC) ? 1 : 0;

    static int smem_set = 0;
    // Immediate API call (not a stream op) — executes identically every launch.
    cudaFuncSetAttribute(k_main, cudaFuncAttributeMaxDynamicSharedMemorySize,
                         CHUNK * 256 * sizeof(float));
    (void)smem_set;

    k0_prep<<<(TT * NB + 255) / 256, 256>>>(cached_len);
    k_main<<<NBLK, 256, CHUNK * 256 * sizeof(float)>>>(x, cached_len, cached_avg,
                                                       out, extras);
}

// round 3
// speedup vs baseline: 2.0485x; 2.0485x over previous
#include <cuda_runtime.h>

// Problem shape (fixed by the dataset)
#define TT 4096
#define NB 16
#define CC 512
#define NC (NB * CC)            // 8192 columns
#define NC4 (NC / 4)            // 2048 float4 columns
#define CHUNK 64
#define NCHUNKS (TT / CHUNK)    // 64
#define TOTAL (TT * NC)         // 33,554,432 floats for new_x

#define KA_SUM_BLOCKS ((NCHUNKS * NC4) / 256)   // 512
#define KA_RCP_BLOCKS ((TT * NB) / 256)         // 256

// Static scratch (no allocations allowed)
__device__ float4 g_agg4[NCHUNKS * NC4];   // 2 MB: per-(chunk, col4) sums (L2-resident)
__device__ float  g_rcp[TT * NB];          // 256 KB: 1/(t+1+len_n), layout [t][n]

// kA: fused — role 1: per-chunk float4 partial sums; role 2: reciprocal table.
__global__ void kA(const float4* __restrict__ x4, const int* __restrict__ cached_len) {
    int bid = blockIdx.x;
    int tid = threadIdx.x;
    if (bid < KA_SUM_BLOCKS) {
        int idx = bid * 256 + tid;                 // 0 .. NCHUNKS*NC4-1
        int nc4 = idx & (NC4 - 1);
        int chunk = idx >> 11;                     // / NC4
        const float4* p = x4 + (size_t)chunk * CHUNK * NC4 + nc4;
        float4 s = make_float4(0.f, 0.f, 0.f, 0.f);
#pragma unroll 8
        for (int i = 0; i < CHUNK; i++) {
            float4 v = p[(size_t)i * NC4];
            s.x += v.x; s.y += v.y; s.z += v.z; s.w += v.w;
        }
        g_agg4[idx] = s;
    } else {
        int idx = (bid - KA_SUM_BLOCKS) * 256 + tid;   // 0 .. TT*NB-1
        int n = idx & (NB - 1);
        int t = idx >> 4;
        g_rcp[idx] = 1.0f / ((float)(t + 1) + (float)cached_len[n]);
    }
}

// kB: final scan. Each thread owns one float4 column within one 64-step chunk.
// Its exclusive base = cached seed + sum of predecessor chunk aggregates
// (independent coalesced L2 loads — no serial scan kernel needed).
__global__ void kB(const float4* __restrict__ x4,
                   const int* __restrict__ cached_len,
                   const float4* __restrict__ avg4,
                   float4* __restrict__ out4, int extras) {
    int idx = blockIdx.x * 256 + threadIdx.x;      // 0 .. NCHUNKS*NC4-1
    int nc4 = idx & (NC4 - 1);
    int chunk = idx >> 11;
    int n = nc4 >> 7;                              // (nc4*4) / 512

    float lenf = (float)cached_len[n];
    float4 base = avg4[nc4];
    base.x *= lenf; base.y *= lenf; base.z *= lenf; base.w *= lenf;

    // Prefix over predecessor chunks (g_agg4 is 2 MB, L2-resident).
#pragma unroll 4
    for (int ch = 0; ch < chunk; ch++) {
        float4 a = g_agg4[ch * NC4 + nc4];
        base.x += a.x; base.y += a.y; base.z += a.z; base.w += a.w;
    }

    const float4* px = x4   + (size_t)chunk * CHUNK * NC4 + nc4;
    float4*       po = out4 + (size_t)chunk * CHUNK * NC4 + nc4;
    const float*  pr = g_rcp + (size_t)chunk * CHUNK * NB + n;   // warp-uniform

    float4 last = make_float4(0.f, 0.f, 0.f, 0.f);
#pragma unroll 8
    for (int i = 0; i < CHUNK; i++) {
        float4 v = px[(size_t)i * NC4];
        base.x += v.x; base.y += v.y; base.z += v.z; base.w += v.w;
        float r = pr[(size_t)i * NB];
        last.x = base.x * r; last.y = base.y * r;
        last.z = base.z * r; last.w = base.w * r;
        po[(size_t)i * NC4] = last;
    }

    if (extras) {
        // Tuple order: [new_x | new_cached_len (as float) | new_cached_avg]
        if (chunk == NCHUNKS - 1)
            out4[(TOTAL + NB) / 4 + nc4] = last;               // new_x[T-1]
        if (idx < NB) {
            float* outf = (float*)out4;
            outf[TOTAL + idx] = (float)(cached_len[idx] + TT);
        }
    }
}

extern "C" void kernel_launch(void* const* d_in, const int* in_sizes, int n_in,
                              void* d_out, int out_size) {
    const float4* x4         = (const float4*)d_in[0];   // (T, N, C)
    const int*    cached_len = (const int*)d_in[1];      // (N,)
    const float4* avg4       = (const float4*)d_in[2];   // (N, C)
    float4* out4 = (float4*)d_out;

    int extras = (out_size >= TOTAL + NB + NC) ? 1 : 0;

    kA<<<KA_SUM_BLOCKS + KA_RCP_BLOCKS, 256>>>(x4, cached_len);
    kB<<<KA_SUM_BLOCKS, 256>>>(x4, cached_len, avg4, out4, extras);
}